// round 6
// baseline (speedup 1.0000x reference)
#include <cuda_runtime.h>
#include <math.h>

#define NBATCH 4
#define NPTS   8192
#define NP     32768   // NBATCH*NPTS
#define KNN    16

#define KT      128            // knn threads per block
#define KSPLIT  2              // candidate slices
#define SLICE   (NPTS/KSPLIT)  // 4096 candidates per slice
#define KCHUNK  2048           // candidates per smem tile
#define KBLK    128            // block size for phase-A minima
#define RING    24             // per-thread ring slots per chunk
#define KNN_SMEM (KCHUNK*16 + RING*KT*4 + RING*KT*4)   // 32KB + 12KB + 12KB = 56KB

// ---------------- scratch (static device globals; no allocs allowed) ----------------
__device__ float4 g_coords4[NP];    // {x, y, z, |p|^2}
__device__ float g_act1[NP*80];     // [f0(64) | coords(3) | zeros(13)]
__device__ int   g_idx[NP*KNN];     // global neighbor indices
__device__ float g_knn_d[NP*KSPLIT*KNN];
__device__ int   g_knn_i[NP*KSPLIT*KNN];
__device__ float g_Wc1[80*256];     // combined stage-1 weights [k][n], n<128 -> a, n>=128 -> c
__device__ float g_bc1[256];
__device__ float g_Wc2[144*512];
__device__ float g_bc2[512];
__device__ float g_ac1[NP*256];     // [a1(128) | c1(128)]
__device__ float g_act2[NP*144];    // [f1(128) | coords(3) | zeros(13)]
__device__ float g_ac2[NP*512];     // [a2(256) | c2(256)]
__device__ float g_f2[NP*256];
__device__ float g_h[NP*256];
__device__ int   g_gmax[NBATCH*256];
__device__ float g_tvec[NBATCH*256];

// ---------------- build combined weights ----------------
__global__ void build_weights(const float* __restrict__ b1w, const float* __restrict__ b1b,
                              const float* __restrict__ b2w, const float* __restrict__ b2b) {
    int t = threadIdx.x;
    for (int i = t; i < 80*256; i += 256) {
        int k = i >> 8, n = i & 255;
        int nc = n & 127; bool isC = n >= 128;
        float v = 0.f;
        if (k < 64) {
            float wa = b1w[k*128 + nc];
            float wb = b1w[(64+k)*128 + nc];
            v = isC ? wb : (wa - wb);
        } else if (k < 67) {
            float wp = b1w[(128 + (k-64))*128 + nc];
            v = isC ? wp : -wp;
        }
        g_Wc1[i] = v;
    }
    for (int n = t; n < 256; n += 256) g_bc1[n] = (n < 128) ? b1b[n] : 0.f;
    for (int i = t; i < 144*512; i += 256) {
        int k = i >> 9, n = i & 511;
        int nc = n & 255; bool isC = n >= 256;
        float v = 0.f;
        if (k < 128) {
            float wa = b2w[k*256 + nc];
            float wb = b2w[(128+k)*256 + nc];
            v = isC ? wb : (wa - wb);
        } else if (k < 131) {
            float wp = b2w[(256 + (k-128))*256 + nc];
            v = isC ? wp : -wp;
        }
        g_Wc2[i] = v;
    }
    for (int n = t; n < 512; n += 256) g_bc2[n] = (n < 256) ? b2b[n] : 0.f;
}

// ---------------- prep: coords + stem ----------------
__global__ void prep_kernel(const float* __restrict__ x,
                            const float* __restrict__ pa, const float* __restrict__ pb,
                            const float* __restrict__ pc,
                            const float* __restrict__ sw, const float* __restrict__ sb) {
    __shared__ float w[256];
    __shared__ float bsh[64];
    if (threadIdx.x < 256) w[threadIdx.x] = sw[threadIdx.x];
    if (threadIdx.x < 64)  bsh[threadIdx.x] = sb[threadIdx.x];
    __syncthreads();
    int i = blockIdx.x * blockDim.x + threadIdx.x;
    if (i >= NP) return;
    float4 xv = ((const float4*)x)[i];
    float z = (*pa) * xv.z + (*pb) * xv.w + (*pc);
    float nsq = fmaf(xv.x, xv.x, fmaf(xv.y, xv.y, z*z));
    g_coords4[i] = make_float4(xv.x, xv.y, z, nsq);
    float* a = &g_act1[i*80];
    #pragma unroll 8
    for (int o = 0; o < 64; o++) {
        float s = bsh[o];
        s = fmaf(xv.x, w[o],      s);
        s = fmaf(xv.y, w[64+o],   s);
        s = fmaf(xv.z, w[128+o],  s);
        s = fmaf(xv.w, w[192+o],  s);
        a[o] = fmaxf(s, 0.f);
    }
    a[64] = xv.x; a[65] = xv.y; a[66] = z;
    #pragma unroll
    for (int o = 67; o < 80; o++) a[o] = 0.f;
}

// ---------------- KNN pass 1: per-slice two-phase exact top-16 ----------------
// Surrogate d' = |p|^2 - 2 q.p (monotone per query in true distance).
// Phase A: 32 block-minima of the slice -> tau = 16th smallest (upper bound on
// the slice's true 16th). Phase B: collect d <= tau via predicated smem ring;
// ring overflow (rare) triggers an exact whole-chunk rescan fallback.
__global__ __launch_bounds__(KT) void knn_slice_kernel() {
    extern __shared__ char sm[];
    float4* tile   = (float4*)sm;                              // KCHUNK float4
    float*  ring_d = (float*)(sm + KCHUNK*16);                 // [RING][KT]
    int*    ring_i = (int*)  (sm + KCHUNK*16 + RING*KT*4);     // [RING][KT]

    int blk   = blockIdx.x;
    int slice = blk & (KSPLIT-1);
    int qblk  = (blk >> 1) & 63;
    int b     = blk >> 7;
    int base  = b*NPTS;
    int sbase = slice*SLICE;

    int n = qblk*KT + threadIdx.x;
    float4 q = g_coords4[base + n];
    float nqx = -2.f*q.x, nqy = -2.f*q.y, nqz = -2.f*q.z;

    // ---- Phase A: threshold over 32 block-minima ----
    float s[KNN];
    #pragma unroll
    for (int t = 0; t < KNN; t++) s[t] = 3.4e38f;

    for (int c = 0; c < SLICE/KCHUNK; c++) {
        __syncthreads();
        for (int i = threadIdx.x; i < KCHUNK; i += KT)
            tile[i] = g_coords4[base + sbase + c*KCHUNK + i];
        __syncthreads();
        for (int bb = 0; bb < KCHUNK/KBLK; bb++) {
            const float4* tb = &tile[bb*KBLK];
            float m0 = 3.4e38f, m1 = 3.4e38f, m2 = 3.4e38f, m3 = 3.4e38f;
            #pragma unroll 4
            for (int j = 0; j < KBLK; j += 4) {
                float4 p0 = tb[j+0], p1 = tb[j+1], p2 = tb[j+2], p3 = tb[j+3];
                m0 = fminf(m0, fmaf(p0.z, nqz, fmaf(p0.y, nqy, fmaf(p0.x, nqx, p0.w))));
                m1 = fminf(m1, fmaf(p1.z, nqz, fmaf(p1.y, nqy, fmaf(p1.x, nqx, p1.w))));
                m2 = fminf(m2, fmaf(p2.z, nqz, fmaf(p2.y, nqy, fmaf(p2.x, nqx, p2.w))));
                m3 = fminf(m3, fmaf(p3.z, nqz, fmaf(p3.y, nqy, fmaf(p3.x, nqx, p3.w))));
            }
            float m = fminf(fminf(m0, m1), fminf(m2, m3));
            #pragma unroll
            for (int t = 0; t < KNN; t++) {       // branchless ascending insert
                float lo = fminf(s[t], m);
                m = fmaxf(s[t], m);
                s[t] = lo;
            }
        }
    }
    float tau = s[KNN-1];
    int tb_ = __float_as_int(tau);
    tb_ += (tau >= 0.f) ? 1 : -1;          // nextafter(tau,+inf): accept d<=tau via d<worst
    float worst = __int_as_float(tb_);

    // ---- Phase B: collect + drain ----
    float bd[KNN]; int bi[KNN];
    #pragma unroll
    for (int t = 0; t < KNN; t++) { bd[t] = worst; bi[t] = 0; }

    for (int c = 0; c < SLICE/KCHUNK; c++) {
        __syncthreads();
        for (int i = threadIdx.x; i < KCHUNK; i += KT)
            tile[i] = g_coords4[base + sbase + c*KCHUNK + i];
        __syncthreads();
        int cnt = 0, dropped = 0;
        int jbase = sbase + c*KCHUNK;
        #pragma unroll 4
        for (int j = 0; j < KCHUNK; j++) {
            float4 p = tile[j];
            float d = fmaf(p.z, nqz, fmaf(p.y, nqy, fmaf(p.x, nqx, p.w)));
            bool acc = (d < worst);
            bool room = acc && (cnt < RING);
            if (room) {
                ring_d[cnt*KT + threadIdx.x] = d;
                ring_i[cnt*KT + threadIdx.x] = jbase + j;
                cnt++;
            }
            dropped |= (acc && !room);
        }
        if (__any_sync(0xFFFFFFFFu, dropped)) {
            // Exact fallback: whole-chunk replace-worst rescan (ring ignored).
            for (int j = 0; j < KCHUNK; j++) {
                float4 p = tile[j];
                float d = fmaf(p.z, nqz, fmaf(p.y, nqy, fmaf(p.x, nqx, p.w)));
                float w = bd[0]; int ws = 0;
                #pragma unroll
                for (int t = 1; t < KNN; t++) if (bd[t] > w) { w = bd[t]; ws = t; }
                if (d < w) { bd[ws] = d; bi[ws] = jbase + j; }
            }
        } else {
            for (int k = 0; k < cnt; k++) {
                float d = ring_d[k*KT + threadIdx.x];
                int  ji = ring_i[k*KT + threadIdx.x];
                float w = bd[0]; int ws = 0;
                #pragma unroll
                for (int t = 1; t < KNN; t++) if (bd[t] > w) { w = bd[t]; ws = t; }
                if (d < w) { bd[ws] = d; bi[ws] = ji; }
            }
        }
        float w = bd[0];
        #pragma unroll
        for (int t = 1; t < KNN; t++) w = fmaxf(w, bd[t]);
        worst = w;
    }

    int obase = ((base + n)*KSPLIT + slice)*KNN;
    #pragma unroll
    for (int t = 0; t < KNN; t++) { g_knn_d[obase + t] = bd[t]; g_knn_i[obase + t] = bi[t]; }
}

// ---------------- KNN pass 2: merge 2 slice lists -> global top-16 set ----------------
__global__ void knn_merge_kernel() {
    int q = blockIdx.x * blockDim.x + threadIdx.x;
    if (q >= NP) return;
    const float* dd = &g_knn_d[q*KSPLIT*KNN];
    const int*   ii = &g_knn_i[q*KSPLIT*KNN];
    float bd[KNN]; int bi[KNN];
    #pragma unroll
    for (int t = 0; t < KNN; t++) { bd[t] = dd[t]; bi[t] = ii[t]; }
    #pragma unroll 4
    for (int e = KNN; e < KSPLIT*KNN; e++) {
        float d = dd[e];
        float w = bd[0]; int ws = 0;
        #pragma unroll
        for (int t = 1; t < KNN; t++) if (bd[t] > w) { w = bd[t]; ws = t; }
        if (d < w) { bd[ws] = d; bi[ws] = ii[e]; }
    }
    int boff = (q >> 13) * NPTS;
    #pragma unroll
    for (int t = 0; t < KNN; t++) g_idx[q*KNN + t] = boff + bi[t];
}

// ---------------- generic fp32 GEMM with packed f32x2 FMA ----------------
// C[M,NT] = act(A[M,KP]@W[KP,NT] + bias).  BM=64, BN=64, BK=16, 256 threads, 4x4/thread.
// Accumulators held as f32x2 pairs; fma.rn.f32x2 = 2 rn-FMAs per instruction
// (bitwise identical to scalar FFMA).
template<int KP, int NT, int BIASMODE, int RELU>
__global__ void gemm_kernel(const float* __restrict__ A, const float* __restrict__ W,
                            const float* __restrict__ bias, float* __restrict__ C) {
    __shared__ float As[64][17];
    __shared__ float Bs[16][64];
    int tid = threadIdx.x;
    int row0 = blockIdx.x * 64;
    int col0 = blockIdx.y * 64;
    int m0 = (tid >> 4) * 4;
    int n0 = (tid & 15) * 4;
    unsigned long long acc01[4], acc23[4];
    #pragma unroll
    for (int i = 0; i < 4; i++) { acc01[i] = 0ULL; acc23[i] = 0ULL; }

    for (int k0 = 0; k0 < KP; k0 += 16) {
        #pragma unroll
        for (int l = tid; l < 64*16; l += 256) {
            int r = l >> 4, kk = l & 15;
            As[r][kk] = A[(row0 + r)*KP + k0 + kk];
        }
        {
            int kk = tid >> 4, c = (tid & 15) * 4;
            float4 wv = *(const float4*)&W[(k0 + kk)*NT + col0 + c];
            *(float4*)&Bs[kk][c] = wv;
        }
        __syncthreads();
        #pragma unroll
        for (int kk = 0; kk < 16; kk++) {
            float a0 = As[m0+0][kk], a1 = As[m0+1][kk], a2 = As[m0+2][kk], a3 = As[m0+3][kk];
            float4 bv = *(float4*)&Bs[kk][n0];
            unsigned long long b01, b23, ap0, ap1, ap2, ap3;
            asm("mov.b64 %0,{%1,%2};" : "=l"(b01) : "f"(bv.x), "f"(bv.y));
            asm("mov.b64 %0,{%1,%2};" : "=l"(b23) : "f"(bv.z), "f"(bv.w));
            asm("mov.b64 %0,{%1,%1};" : "=l"(ap0) : "f"(a0));
            asm("mov.b64 %0,{%1,%1};" : "=l"(ap1) : "f"(a1));
            asm("mov.b64 %0,{%1,%1};" : "=l"(ap2) : "f"(a2));
            asm("mov.b64 %0,{%1,%1};" : "=l"(ap3) : "f"(a3));
            asm("fma.rn.f32x2 %0,%1,%2,%0;" : "+l"(acc01[0]) : "l"(ap0), "l"(b01));
            asm("fma.rn.f32x2 %0,%1,%2,%0;" : "+l"(acc23[0]) : "l"(ap0), "l"(b23));
            asm("fma.rn.f32x2 %0,%1,%2,%0;" : "+l"(acc01[1]) : "l"(ap1), "l"(b01));
            asm("fma.rn.f32x2 %0,%1,%2,%0;" : "+l"(acc23[1]) : "l"(ap1), "l"(b23));
            asm("fma.rn.f32x2 %0,%1,%2,%0;" : "+l"(acc01[2]) : "l"(ap2), "l"(b01));
            asm("fma.rn.f32x2 %0,%1,%2,%0;" : "+l"(acc23[2]) : "l"(ap2), "l"(b23));
            asm("fma.rn.f32x2 %0,%1,%2,%0;" : "+l"(acc01[3]) : "l"(ap3), "l"(b01));
            asm("fma.rn.f32x2 %0,%1,%2,%0;" : "+l"(acc23[3]) : "l"(ap3), "l"(b23));
        }
        __syncthreads();
    }
    #pragma unroll
    for (int i = 0; i < 4; i++) {
        int row = row0 + m0 + i;
        float a0, a1, a2, a3;
        asm("mov.b64 {%0,%1},%2;" : "=f"(a0), "=f"(a1) : "l"(acc01[i]));
        asm("mov.b64 {%0,%1},%2;" : "=f"(a2), "=f"(a3) : "l"(acc23[i]));
        float bx[4];
        #pragma unroll
        for (int j = 0; j < 4; j++) {
            int col = col0 + n0 + j;
            bx[j] = (BIASMODE == 0) ? bias[col] : bias[(row >> 13)*256 + col];
        }
        float4 r;
        r.x = a0 + bx[0]; r.y = a1 + bx[1];
        r.z = a2 + bx[2]; r.w = a3 + bx[3];
        if (RELU) {
            r.x = fmaxf(r.x, 0.f); r.y = fmaxf(r.y, 0.f);
            r.z = fmaxf(r.z, 0.f); r.w = fmaxf(r.w, 0.f);
        }
        *(float4*)&C[row*NT + col0 + n0] = r;
    }
}

// ---------------- gather-max stage 1 ----------------
__global__ void gather1_kernel() {
    int wid  = (blockIdx.x * blockDim.x + threadIdx.x) >> 5;
    int lane = threadIdx.x & 31;
    if (wid >= NP) return;
    const int* idx = &g_idx[wid*KNN];
    float4 mv = make_float4(-3.4e38f, -3.4e38f, -3.4e38f, -3.4e38f);
    #pragma unroll
    for (int t = 0; t < KNN; t++) {
        int j = idx[t];
        float4 v = *(const float4*)&g_ac1[j*256 + 128 + lane*4];
        mv.x = fmaxf(mv.x, v.x); mv.y = fmaxf(mv.y, v.y);
        mv.z = fmaxf(mv.z, v.z); mv.w = fmaxf(mv.w, v.w);
    }
    float4 a = *(const float4*)&g_ac1[wid*256 + lane*4];
    float4 o;
    o.x = fmaxf(a.x + mv.x, 0.f); o.y = fmaxf(a.y + mv.y, 0.f);
    o.z = fmaxf(a.z + mv.z, 0.f); o.w = fmaxf(a.w + mv.w, 0.f);
    *(float4*)&g_act2[wid*144 + lane*4] = o;
    if (lane < 16) {
        float v = (lane < 3) ? ((const float*)g_coords4)[wid*4 + lane] : 0.f;
        g_act2[wid*144 + 128 + lane] = v;
    }
}

// ---------------- gather-max stage 2 ----------------
__global__ void gather2_kernel() {
    int wid  = (blockIdx.x * blockDim.x + threadIdx.x) >> 5;
    int lane = threadIdx.x & 31;
    if (wid >= NP) return;
    const int* idx = &g_idx[wid*KNN];
    float4 m0 = make_float4(-3.4e38f, -3.4e38f, -3.4e38f, -3.4e38f);
    float4 m1 = m0;
    #pragma unroll
    for (int t = 0; t < KNN; t++) {
        int j = idx[t];
        float4 v0 = *(const float4*)&g_ac2[j*512 + 256 + lane*4];
        float4 v1 = *(const float4*)&g_ac2[j*512 + 384 + lane*4];
        m0.x = fmaxf(m0.x, v0.x); m0.y = fmaxf(m0.y, v0.y);
        m0.z = fmaxf(m0.z, v0.z); m0.w = fmaxf(m0.w, v0.w);
        m1.x = fmaxf(m1.x, v1.x); m1.y = fmaxf(m1.y, v1.y);
        m1.z = fmaxf(m1.z, v1.z); m1.w = fmaxf(m1.w, v1.w);
    }
    float4 a0 = *(const float4*)&g_ac2[wid*512 + lane*4];
    float4 a1 = *(const float4*)&g_ac2[wid*512 + 128 + lane*4];
    float4 o0, o1;
    o0.x = fmaxf(a0.x + m0.x, 0.f); o0.y = fmaxf(a0.y + m0.y, 0.f);
    o0.z = fmaxf(a0.z + m0.z, 0.f); o0.w = fmaxf(a0.w + m0.w, 0.f);
    o1.x = fmaxf(a1.x + m1.x, 0.f); o1.y = fmaxf(a1.y + m1.y, 0.f);
    o1.z = fmaxf(a1.z + m1.z, 0.f); o1.w = fmaxf(a1.w + m1.w, 0.f);
    *(float4*)&g_f2[wid*256 + lane*4]       = o0;
    *(float4*)&g_f2[wid*256 + 128 + lane*4] = o1;
}

// ---------------- global max pooling ----------------
__global__ void zero_gmax_kernel() {
    int i = threadIdx.x;
    if (i < NBATCH*256) g_gmax[i] = 0;   // 0.0f bits; all f2 >= 0
}

__global__ void colmax_kernel() {
    int b = blockIdx.x >> 5;
    int chunk = blockIdx.x & 31;
    int c = threadIdx.x;
    int base = b*NPTS + chunk*256;
    float m = 0.f;
    #pragma unroll 4
    for (int p = 0; p < 256; p++) m = fmaxf(m, g_f2[(base + p)*256 + c]);
    atomicMax(&g_gmax[b*256 + c], __float_as_int(m));
}

// ---------------- per-batch vectors ----------------
__global__ void batchvec_kernel(const float* __restrict__ globw, const float* __restrict__ globb,
                                const float* __restrict__ h1w, const float* __restrict__ h1b) {
    int b = blockIdx.x, n = threadIdx.x;
    __shared__ float gm[256], gg[256];
    gm[n] = __int_as_float(g_gmax[b*256 + n]);
    __syncthreads();
    float s = globb[n];
    #pragma unroll 8
    for (int k = 0; k < 256; k++) s = fmaf(gm[k], globw[k*256 + n], s);
    gg[n] = fmaxf(s, 0.f);
    __syncthreads();
    float t = h1b[n];
    #pragma unroll 8
    for (int k = 0; k < 256; k++) t = fmaf(gg[k], h1w[(256 + k)*256 + n], t);
    g_tvec[b*256 + n] = t;
}

// ---------------- final head ----------------
__global__ void final_kernel(const float* __restrict__ x,
                             const float* __restrict__ h2w, const float* __restrict__ h2b,
                             const float* __restrict__ pthresh, const float* __restrict__ psharp,
                             const float* __restrict__ pscale, float* __restrict__ out) {
    int wid  = (blockIdx.x * blockDim.x + threadIdx.x) >> 5;
    int lane = threadIdx.x & 31;
    if (wid >= NP) return;
    const float* h = &g_h[wid*256];
    float s0 = 0.f, s1 = 0.f, s2 = 0.f;
    #pragma unroll
    for (int m = 0; m < 8; m++) {
        int k = lane + 32*m;
        float hv = h[k];
        s0 = fmaf(hv, h2w[k*3+0], s0);
        s1 = fmaf(hv, h2w[k*3+1], s1);
        s2 = fmaf(hv, h2w[k*3+2], s2);
    }
    #pragma unroll
    for (int o = 16; o; o >>= 1) {
        s0 += __shfl_down_sync(0xFFFFFFFFu, s0, o);
        s1 += __shfl_down_sync(0xFFFFFFFFu, s1, o);
        s2 += __shfl_down_sync(0xFFFFFFFFu, s2, o);
    }
    if (lane == 0) {
        float hag = x[wid*4 + 3];
        float t = (*psharp) * ((*pthresh) - hag);
        float bias = (*pscale) / (1.f + expf(-t));
        out[wid*3+0] = s0 + h2b[0] + bias;
        out[wid*3+1] = s1 + h2b[1];
        out[wid*3+2] = s2 + h2b[2];
    }
}

// ---------------- launch ----------------
extern "C" void kernel_launch(void* const* d_in, const int* in_sizes, int n_in,
                              void* d_out, int out_size) {
    const float* x      = (const float*)d_in[0];
    const float* hmix_a = (const float*)d_in[1];
    const float* hmix_b = (const float*)d_in[2];
    const float* hmix_c = (const float*)d_in[3];
    const float* stem_w = (const float*)d_in[4];
    const float* stem_b = (const float*)d_in[5];
    const float* b1_w   = (const float*)d_in[6];
    const float* b1_b   = (const float*)d_in[7];
    const float* b2_w   = (const float*)d_in[8];
    const float* b2_b   = (const float*)d_in[9];
    const float* glob_w = (const float*)d_in[10];
    const float* glob_b = (const float*)d_in[11];
    const float* h1_w   = (const float*)d_in[12];
    const float* h1_b   = (const float*)d_in[13];
    const float* h2_w   = (const float*)d_in[14];
    const float* h2_b   = (const float*)d_in[15];
    const float* thresh = (const float*)d_in[16];
    const float* sharp  = (const float*)d_in[17];
    const float* scale  = (const float*)d_in[18];
    float* out = (float*)d_out;

    void *p_act1, *p_Wc1, *p_bc1, *p_ac1, *p_act2, *p_Wc2, *p_bc2, *p_ac2, *p_f2, *p_tvec, *p_h;
    cudaGetSymbolAddress(&p_act1, g_act1);
    cudaGetSymbolAddress(&p_Wc1,  g_Wc1);
    cudaGetSymbolAddress(&p_bc1,  g_bc1);
    cudaGetSymbolAddress(&p_ac1,  g_ac1);
    cudaGetSymbolAddress(&p_act2, g_act2);
    cudaGetSymbolAddress(&p_Wc2,  g_Wc2);
    cudaGetSymbolAddress(&p_bc2,  g_bc2);
    cudaGetSymbolAddress(&p_ac2,  g_ac2);
    cudaGetSymbolAddress(&p_f2,   g_f2);
    cudaGetSymbolAddress(&p_tvec, g_tvec);
    cudaGetSymbolAddress(&p_h,    g_h);

    cudaFuncSetAttribute(knn_slice_kernel, cudaFuncAttributeMaxDynamicSharedMemorySize, KNN_SMEM);

    build_weights<<<1, 256>>>(b1_w, b1_b, b2_w, b2_b);
    prep_kernel<<<NP/256, 256>>>(x, hmix_a, hmix_b, hmix_c, stem_w, stem_b);
    zero_gmax_kernel<<<1, 1024>>>();
    knn_slice_kernel<<<NBATCH*64*KSPLIT, KT, KNN_SMEM>>>();
    knn_merge_kernel<<<NP/KT, KT>>>();

    gemm_kernel<80, 256, 0, 0><<<dim3(NP/64, 256/64), 256>>>(
        (const float*)p_act1, (const float*)p_Wc1, (const float*)p_bc1, (float*)p_ac1);
    gather1_kernel<<<NP*32/256, 256>>>();

    gemm_kernel<144, 512, 0, 0><<<dim3(NP/64, 512/64), 256>>>(
        (const float*)p_act2, (const float*)p_Wc2, (const float*)p_bc2, (float*)p_ac2);
    gather2_kernel<<<NP*32/256, 256>>>();

    colmax_kernel<<<NBATCH*32, 256>>>();
    batchvec_kernel<<<NBATCH, 256>>>(glob_w, glob_b, h1_w, h1_b);

    gemm_kernel<256, 256, 1, 1><<<dim3(NP/64, 256/64), 256>>>(
        (const float*)p_f2, h1_w, (const float*)p_tvec, (float*)p_h);

    final_kernel<<<NP*32/256, 256>>>(x, h2_w, h2_b, thresh, sharp, scale, out);
    (void)in_sizes; (void)n_in; (void)out_size;
}

// round 8
// speedup vs baseline: 1.3854x; 1.3854x over previous
#include <cuda_runtime.h>
#include <math.h>

#define NBATCH 4
#define NPTS   8192
#define NP     32768   // NBATCH*NPTS
#define KNN    16

#define KT      128            // knn threads per block
#define KCHUNK  2048           // candidates per smem tile
#define NCHUNK  (NPTS/KCHUNK)  // 4
#define KBLK    128            // block size for phase-A minima (64 minima total)
#define RING    32             // ring slots per thread per chunk (16 per stream)
#define KNN_SMEM (KCHUNK*16 + RING*KT*4 + RING*KT*4)   // 32KB + 16KB + 16KB

// ---------------- scratch (static device globals; no allocs allowed) ----------------
__device__ float4 g_coords4[NP];    // {x, y, z, |p|^2}
__device__ float g_act1[NP*80];     // [f0(64) | coords(3) | zeros(13)]
__device__ int   g_idx[NP*KNN];     // global neighbor indices
__device__ float g_Wc1[80*256];     // combined stage-1 weights [k][n], n<128 -> a, n>=128 -> c
__device__ float g_bc1[256];
__device__ float g_Wc2[144*512];
__device__ float g_bc2[512];
__device__ float g_ac1[NP*256];     // [a1(128) | c1(128)]
__device__ float g_act2[NP*144];    // [f1(128) | coords(3) | zeros(13)]
__device__ float g_ac2[NP*512];     // [a2(256) | c2(256)]
__device__ float g_f2[NP*256];
__device__ float g_h[NP*256];
__device__ int   g_gmax[NBATCH*256];
__device__ float g_tvec[NBATCH*256];

// ---------------- build combined weights ----------------
__global__ void build_weights(const float* __restrict__ b1w, const float* __restrict__ b1b,
                              const float* __restrict__ b2w, const float* __restrict__ b2b) {
    int t = threadIdx.x;
    for (int i = t; i < 80*256; i += 256) {
        int k = i >> 8, n = i & 255;
        int nc = n & 127; bool isC = n >= 128;
        float v = 0.f;
        if (k < 64) {
            float wa = b1w[k*128 + nc];
            float wb = b1w[(64+k)*128 + nc];
            v = isC ? wb : (wa - wb);
        } else if (k < 67) {
            float wp = b1w[(128 + (k-64))*128 + nc];
            v = isC ? wp : -wp;
        }
        g_Wc1[i] = v;
    }
    for (int n = t; n < 256; n += 256) g_bc1[n] = (n < 128) ? b1b[n] : 0.f;
    for (int i = t; i < 144*512; i += 256) {
        int k = i >> 9, n = i & 511;
        int nc = n & 255; bool isC = n >= 256;
        float v = 0.f;
        if (k < 128) {
            float wa = b2w[k*256 + nc];
            float wb = b2w[(128+k)*256 + nc];
            v = isC ? wb : (wa - wb);
        } else if (k < 131) {
            float wp = b2w[(256 + (k-128))*256 + nc];
            v = isC ? wp : -wp;
        }
        g_Wc2[i] = v;
    }
    for (int n = t; n < 512; n += 256) g_bc2[n] = (n < 256) ? b2b[n] : 0.f;
}

// ---------------- prep: coords + stem ----------------
__global__ void prep_kernel(const float* __restrict__ x,
                            const float* __restrict__ pa, const float* __restrict__ pb,
                            const float* __restrict__ pc,
                            const float* __restrict__ sw, const float* __restrict__ sb) {
    __shared__ float w[256];
    __shared__ float bsh[64];
    if (threadIdx.x < 256) w[threadIdx.x] = sw[threadIdx.x];
    if (threadIdx.x < 64)  bsh[threadIdx.x] = sb[threadIdx.x];
    __syncthreads();
    int i = blockIdx.x * blockDim.x + threadIdx.x;
    if (i >= NP) return;
    float4 xv = ((const float4*)x)[i];
    float z = (*pa) * xv.z + (*pb) * xv.w + (*pc);
    float nsq = fmaf(xv.x, xv.x, fmaf(xv.y, xv.y, z*z));
    g_coords4[i] = make_float4(xv.x, xv.y, z, nsq);
    float* a = &g_act1[i*80];
    #pragma unroll 8
    for (int o = 0; o < 64; o++) {
        float s = bsh[o];
        s = fmaf(xv.x, w[o],      s);
        s = fmaf(xv.y, w[64+o],   s);
        s = fmaf(xv.z, w[128+o],  s);
        s = fmaf(xv.w, w[192+o],  s);
        a[o] = fmaxf(s, 0.f);
    }
    a[64] = xv.x; a[65] = xv.y; a[66] = z;
    #pragma unroll
    for (int o = 67; o < 80; o++) a[o] = 0.f;
}

// ---------------- KNN: two-phase threshold + dual-stream ring collection ----------------
// Surrogate d' = |p|^2 - 2 q.p (monotone per query in true distance).
// Phase A: 64 block-minima -> tau = 16th smallest block-min (upper bound on true 16th).
// Phase B: two independent streams per thread (chunk halves) for ILP; predicated
// smem ring push; drain per chunk into top-16 regs; threshold tightens per chunk.
__global__ __launch_bounds__(KT) void knn_kernel() {
    extern __shared__ char sm[];
    float4* tile   = (float4*)sm;                              // KCHUNK float4
    float*  ring_d = (float*)(sm + KCHUNK*16);                 // [RING][KT]
    int*    ring_i = (int*)  (sm + KCHUNK*16 + RING*KT*4);     // [RING][KT]

    int b    = blockIdx.x >> 6;                 // 64 query-blocks per batch
    int n    = (blockIdx.x & 63)*KT + threadIdx.x;
    int base = b*NPTS;
    float4 q = g_coords4[base + n];
    float nqx = -2.f*q.x, nqy = -2.f*q.y, nqz = -2.f*q.z;

    // ---- Phase A: threshold ----
    float s[KNN];
    #pragma unroll
    for (int t = 0; t < KNN; t++) s[t] = 3.4e38f;

    for (int c = 0; c < NCHUNK; c++) {
        __syncthreads();
        for (int i = threadIdx.x; i < KCHUNK; i += KT)
            tile[i] = g_coords4[base + c*KCHUNK + i];
        __syncthreads();
        for (int blk = 0; blk < KCHUNK/KBLK; blk++) {
            const float4* tb = &tile[blk*KBLK];
            float m0 = 3.4e38f, m1 = 3.4e38f, m2 = 3.4e38f, m3 = 3.4e38f;
            #pragma unroll 4
            for (int j = 0; j < KBLK; j += 4) {
                float4 p0 = tb[j+0], p1 = tb[j+1], p2 = tb[j+2], p3 = tb[j+3];
                m0 = fminf(m0, fmaf(p0.z, nqz, fmaf(p0.y, nqy, fmaf(p0.x, nqx, p0.w))));
                m1 = fminf(m1, fmaf(p1.z, nqz, fmaf(p1.y, nqy, fmaf(p1.x, nqx, p1.w))));
                m2 = fminf(m2, fmaf(p2.z, nqz, fmaf(p2.y, nqy, fmaf(p2.x, nqx, p2.w))));
                m3 = fminf(m3, fmaf(p3.z, nqz, fmaf(p3.y, nqy, fmaf(p3.x, nqx, p3.w))));
            }
            float m = fminf(fminf(m0, m1), fminf(m2, m3));
            // branchless insert into 16 smallest (s ascending)
            #pragma unroll
            for (int t = 0; t < KNN; t++) {
                float lo = fminf(s[t], m);
                m = fmaxf(s[t], m);
                s[t] = lo;
            }
        }
    }
    float tau = s[KNN-1];
    int tb_ = __float_as_int(tau);
    tb_ += (tau >= 0.f) ? 1 : -1;          // nextafter(tau, +inf): accept d <= tau via d < worst
    float worst = __int_as_float(tb_);

    // ---- Phase B: dual-stream collect + drain ----
    float bd[KNN]; int bi[KNN];
    #pragma unroll
    for (int t = 0; t < KNN; t++) { bd[t] = worst; bi[t] = 0; }

    for (int c = 0; c < NCHUNK; c++) {
        __syncthreads();
        for (int i = threadIdx.x; i < KCHUNK; i += KT)
            tile[i] = g_coords4[base + c*KCHUNK + i];
        __syncthreads();
        int cnt0 = 0, cnt1 = 0;
        int jbase = c*KCHUNK;
        #pragma unroll 4
        for (int j = 0; j < KCHUNK/2; j++) {
            float4 p0 = tile[j];
            float4 p1 = tile[j + KCHUNK/2];
            float d0 = fmaf(p0.z, nqz, fmaf(p0.y, nqy, fmaf(p0.x, nqx, p0.w)));
            float d1 = fmaf(p1.z, nqz, fmaf(p1.y, nqy, fmaf(p1.x, nqx, p1.w)));
            if (d0 < worst && cnt0 < RING/2) {
                ring_d[cnt0*KT + threadIdx.x] = d0;
                ring_i[cnt0*KT + threadIdx.x] = jbase + j;
                cnt0++;
            }
            if (d1 < worst && cnt1 < RING/2) {
                ring_d[(RING/2 + cnt1)*KT + threadIdx.x] = d1;
                ring_i[(RING/2 + cnt1)*KT + threadIdx.x] = jbase + j + KCHUNK/2;
                cnt1++;
            }
        }
        // drain rings into top-16 registers (rare, small)
        for (int k = 0; k < cnt0; k++) {
            float d = ring_d[k*KT + threadIdx.x];
            int  ji = ring_i[k*KT + threadIdx.x];
            float w = bd[0]; int ws = 0;
            #pragma unroll
            for (int t = 1; t < KNN; t++) if (bd[t] > w) { w = bd[t]; ws = t; }
            if (d < w) { bd[ws] = d; bi[ws] = ji; }
        }
        for (int k = 0; k < cnt1; k++) {
            float d = ring_d[(RING/2 + k)*KT + threadIdx.x];
            int  ji = ring_i[(RING/2 + k)*KT + threadIdx.x];
            float w = bd[0]; int ws = 0;
            #pragma unroll
            for (int t = 1; t < KNN; t++) if (bd[t] > w) { w = bd[t]; ws = t; }
            if (d < w) { bd[ws] = d; bi[ws] = ji; }
        }
        // tighten threshold
        float w = bd[0];
        #pragma unroll
        for (int t = 1; t < KNN; t++) w = fmaxf(w, bd[t]);
        worst = w;
    }

    int qg = base + n;
    #pragma unroll
    for (int t = 0; t < KNN; t++) g_idx[qg*KNN + t] = base + bi[t];
}

// ---------------- fp32 GEMM: C[M,NT] = act(A[M,KP]@W[KP,NT] + bias) ----------------
// BM=128, BN=64, BK=16, 256 threads, 8x4 per thread. As stored k-major for LDS.128.
// BIASMODE 0: bias[n]; 1: bias[(row>>13)*256 + n] (per-batch vector, NT must be 256)
template<int KP, int NT, int BIASMODE, int RELU>
__global__ __launch_bounds__(256) void gemm_kernel(const float* __restrict__ A,
                                                   const float* __restrict__ W,
                                                   const float* __restrict__ bias,
                                                   float* __restrict__ C) {
    __shared__ float As[16][132];   // k-major; 132*4=528B rows (16B aligned)
    __shared__ float Bs[16][64];
    int tid = threadIdx.x;
    int row0 = blockIdx.x * 128;
    int col0 = blockIdx.y * 64;
    int m0 = (tid >> 4) * 8;
    int n0 = (tid & 15) * 4;
    float acc[8][4];
    #pragma unroll
    for (int i = 0; i < 8; i++)
        #pragma unroll
        for (int j = 0; j < 4; j++) acc[i][j] = 0.f;

    for (int k0 = 0; k0 < KP; k0 += 16) {
        // load A tile 128x16 (512 float4 across 256 threads, transposed into As)
        #pragma unroll
        for (int i = 0; i < 2; i++) {
            int lin = tid + i*256;
            int r = lin >> 2, kc = (lin & 3) * 4;
            float4 av = *(const float4*)&A[(row0 + r)*KP + k0 + kc];
            As[kc+0][r] = av.x; As[kc+1][r] = av.y;
            As[kc+2][r] = av.z; As[kc+3][r] = av.w;
        }
        // load W tile 16x64
        {
            int kk = tid >> 4, cc = (tid & 15) * 4;
            *(float4*)&Bs[kk][cc] = *(const float4*)&W[(k0 + kk)*NT + col0 + cc];
        }
        __syncthreads();
        #pragma unroll
        for (int kk = 0; kk < 16; kk++) {
            float4 a0 = *(float4*)&As[kk][m0];
            float4 a1 = *(float4*)&As[kk][m0+4];
            float4 bv = *(float4*)&Bs[kk][n0];
            float ar[8] = {a0.x, a0.y, a0.z, a0.w, a1.x, a1.y, a1.z, a1.w};
            #pragma unroll
            for (int i = 0; i < 8; i++) {
                acc[i][0] = fmaf(ar[i], bv.x, acc[i][0]);
                acc[i][1] = fmaf(ar[i], bv.y, acc[i][1]);
                acc[i][2] = fmaf(ar[i], bv.z, acc[i][2]);
                acc[i][3] = fmaf(ar[i], bv.w, acc[i][3]);
            }
        }
        __syncthreads();
    }
    #pragma unroll
    for (int i = 0; i < 8; i++) {
        int row = row0 + m0 + i;
        float bx[4];
        #pragma unroll
        for (int j = 0; j < 4; j++) {
            int col = col0 + n0 + j;
            bx[j] = (BIASMODE == 0) ? bias[col] : bias[(row >> 13)*256 + col];
        }
        float4 r;
        r.x = acc[i][0] + bx[0]; r.y = acc[i][1] + bx[1];
        r.z = acc[i][2] + bx[2]; r.w = acc[i][3] + bx[3];
        if (RELU) {
            r.x = fmaxf(r.x, 0.f); r.y = fmaxf(r.y, 0.f);
            r.z = fmaxf(r.z, 0.f); r.w = fmaxf(r.w, 0.f);
        }
        *(float4*)&C[row*NT + col0 + n0] = r;
    }
}

// ---------------- gather-max stage 1 ----------------
__global__ void gather1_kernel() {
    int wid  = (blockIdx.x * blockDim.x + threadIdx.x) >> 5;
    int lane = threadIdx.x & 31;
    if (wid >= NP) return;
    const int* idx = &g_idx[wid*KNN];
    float4 mv = make_float4(-3.4e38f, -3.4e38f, -3.4e38f, -3.4e38f);
    #pragma unroll
    for (int t = 0; t < KNN; t++) {
        int j = idx[t];
        float4 v = *(const float4*)&g_ac1[j*256 + 128 + lane*4];
        mv.x = fmaxf(mv.x, v.x); mv.y = fmaxf(mv.y, v.y);
        mv.z = fmaxf(mv.z, v.z); mv.w = fmaxf(mv.w, v.w);
    }
    float4 a = *(const float4*)&g_ac1[wid*256 + lane*4];
    float4 o;
    o.x = fmaxf(a.x + mv.x, 0.f); o.y = fmaxf(a.y + mv.y, 0.f);
    o.z = fmaxf(a.z + mv.z, 0.f); o.w = fmaxf(a.w + mv.w, 0.f);
    *(float4*)&g_act2[wid*144 + lane*4] = o;
    if (lane < 16) {
        float v = (lane < 3) ? ((const float*)g_coords4)[wid*4 + lane] : 0.f;
        g_act2[wid*144 + 128 + lane] = v;
    }
}

// ---------------- gather-max stage 2 ----------------
__global__ void gather2_kernel() {
    int wid  = (blockIdx.x * blockDim.x + threadIdx.x) >> 5;
    int lane = threadIdx.x & 31;
    if (wid >= NP) return;
    const int* idx = &g_idx[wid*KNN];
    float4 m0 = make_float4(-3.4e38f, -3.4e38f, -3.4e38f, -3.4e38f);
    float4 m1 = m0;
    #pragma unroll
    for (int t = 0; t < KNN; t++) {
        int j = idx[t];
        float4 v0 = *(const float4*)&g_ac2[j*512 + 256 + lane*4];
        float4 v1 = *(const float4*)&g_ac2[j*512 + 384 + lane*4];
        m0.x = fmaxf(m0.x, v0.x); m0.y = fmaxf(m0.y, v0.y);
        m0.z = fmaxf(m0.z, v0.z); m0.w = fmaxf(m0.w, v0.w);
        m1.x = fmaxf(m1.x, v1.x); m1.y = fmaxf(m1.y, v1.y);
        m1.z = fmaxf(m1.z, v1.z); m1.w = fmaxf(m1.w, v1.w);
    }
    float4 a0 = *(const float4*)&g_ac2[wid*512 + lane*4];
    float4 a1 = *(const float4*)&g_ac2[wid*512 + 128 + lane*4];
    float4 o0, o1;
    o0.x = fmaxf(a0.x + m0.x, 0.f); o0.y = fmaxf(a0.y + m0.y, 0.f);
    o0.z = fmaxf(a0.z + m0.z, 0.f); o0.w = fmaxf(a0.w + m0.w, 0.f);
    o1.x = fmaxf(a1.x + m1.x, 0.f); o1.y = fmaxf(a1.y + m1.y, 0.f);
    o1.z = fmaxf(a1.z + m1.z, 0.f); o1.w = fmaxf(a1.w + m1.w, 0.f);
    *(float4*)&g_f2[wid*256 + lane*4]       = o0;
    *(float4*)&g_f2[wid*256 + 128 + lane*4] = o1;
}

// ---------------- global max pooling ----------------
__global__ void zero_gmax_kernel() {
    int i = threadIdx.x;
    if (i < NBATCH*256) g_gmax[i] = 0;   // 0.0f bits; all f2 >= 0
}

__global__ void colmax_kernel() {
    int b = blockIdx.x >> 5;
    int chunk = blockIdx.x & 31;
    int c = threadIdx.x;
    int base = b*NPTS + chunk*256;
    float m = 0.f;
    #pragma unroll 4
    for (int p = 0; p < 256; p++) m = fmaxf(m, g_f2[(base + p)*256 + c]);
    atomicMax(&g_gmax[b*256 + c], __float_as_int(m));
}

// ---------------- per-batch vectors ----------------
__global__ void batchvec_kernel(const float* __restrict__ globw, const float* __restrict__ globb,
                                const float* __restrict__ h1w, const float* __restrict__ h1b) {
    int b = blockIdx.x, n = threadIdx.x;
    __shared__ float gm[256], gg[256];
    gm[n] = __int_as_float(g_gmax[b*256 + n]);
    __syncthreads();
    float s = globb[n];
    #pragma unroll 8
    for (int k = 0; k < 256; k++) s = fmaf(gm[k], globw[k*256 + n], s);
    gg[n] = fmaxf(s, 0.f);
    __syncthreads();
    float t = h1b[n];
    #pragma unroll 8
    for (int k = 0; k < 256; k++) t = fmaf(gg[k], h1w[(256 + k)*256 + n], t);
    g_tvec[b*256 + n] = t;
}

// ---------------- final head ----------------
__global__ void final_kernel(const float* __restrict__ x,
                             const float* __restrict__ h2w, const float* __restrict__ h2b,
                             const float* __restrict__ pthresh, const float* __restrict__ psharp,
                             const float* __restrict__ pscale, float* __restrict__ out) {
    int wid  = (blockIdx.x * blockDim.x + threadIdx.x) >> 5;
    int lane = threadIdx.x & 31;
    if (wid >= NP) return;
    const float* h = &g_h[wid*256];
    float s0 = 0.f, s1 = 0.f, s2 = 0.f;
    #pragma unroll
    for (int m = 0; m < 8; m++) {
        int k = lane + 32*m;
        float hv = h[k];
        s0 = fmaf(hv, h2w[k*3+0], s0);
        s1 = fmaf(hv, h2w[k*3+1], s1);
        s2 = fmaf(hv, h2w[k*3+2], s2);
    }
    #pragma unroll
    for (int o = 16; o; o >>= 1) {
        s0 += __shfl_down_sync(0xFFFFFFFFu, s0, o);
        s1 += __shfl_down_sync(0xFFFFFFFFu, s1, o);
        s2 += __shfl_down_sync(0xFFFFFFFFu, s2, o);
    }
    if (lane == 0) {
        float hag = x[wid*4 + 3];
        float t = (*psharp) * ((*pthresh) - hag);
        float bias = (*pscale) / (1.f + expf(-t));
        out[wid*3+0] = s0 + h2b[0] + bias;
        out[wid*3+1] = s1 + h2b[1];
        out[wid*3+2] = s2 + h2b[2];
    }
}

// ---------------- launch ----------------
extern "C" void kernel_launch(void* const* d_in, const int* in_sizes, int n_in,
                              void* d_out, int out_size) {
    const float* x      = (const float*)d_in[0];
    const float* hmix_a = (const float*)d_in[1];
    const float* hmix_b = (const float*)d_in[2];
    const float* hmix_c = (const float*)d_in[3];
    const float* stem_w = (const float*)d_in[4];
    const float* stem_b = (const float*)d_in[5];
    const float* b1_w   = (const float*)d_in[6];
    const float* b1_b   = (const float*)d_in[7];
    const float* b2_w   = (const float*)d_in[8];
    const float* b2_b   = (const float*)d_in[9];
    const float* glob_w = (const float*)d_in[10];
    const float* glob_b = (const float*)d_in[11];
    const float* h1_w   = (const float*)d_in[12];
    const float* h1_b   = (const float*)d_in[13];
    const float* h2_w   = (const float*)d_in[14];
    const float* h2_b   = (const float*)d_in[15];
    const float* thresh = (const float*)d_in[16];
    const float* sharp  = (const float*)d_in[17];
    const float* scale  = (const float*)d_in[18];
    float* out = (float*)d_out;

    void *p_act1, *p_Wc1, *p_bc1, *p_ac1, *p_act2, *p_Wc2, *p_bc2, *p_ac2, *p_f2, *p_tvec, *p_h;
    cudaGetSymbolAddress(&p_act1, g_act1);
    cudaGetSymbolAddress(&p_Wc1,  g_Wc1);
    cudaGetSymbolAddress(&p_bc1,  g_bc1);
    cudaGetSymbolAddress(&p_ac1,  g_ac1);
    cudaGetSymbolAddress(&p_act2, g_act2);
    cudaGetSymbolAddress(&p_Wc2,  g_Wc2);
    cudaGetSymbolAddress(&p_bc2,  g_bc2);
    cudaGetSymbolAddress(&p_ac2,  g_ac2);
    cudaGetSymbolAddress(&p_f2,   g_f2);
    cudaGetSymbolAddress(&p_tvec, g_tvec);
    cudaGetSymbolAddress(&p_h,    g_h);

    cudaFuncSetAttribute(knn_kernel, cudaFuncAttributeMaxDynamicSharedMemorySize, KNN_SMEM);

    build_weights<<<1, 256>>>(b1_w, b1_b, b2_w, b2_b);
    prep_kernel<<<NP/256, 256>>>(x, hmix_a, hmix_b, hmix_c, stem_w, stem_b);
    zero_gmax_kernel<<<1, 1024>>>();
    knn_kernel<<<NBATCH*64, KT, KNN_SMEM>>>();

    gemm_kernel<80, 256, 0, 0><<<dim3(NP/128, 256/64), 256>>>(
        (const float*)p_act1, (const float*)p_Wc1, (const float*)p_bc1, (float*)p_ac1);
    gather1_kernel<<<NP*32/256, 256>>>();

    gemm_kernel<144, 512, 0, 0><<<dim3(NP/128, 512/64), 256>>>(
        (const float*)p_act2, (const float*)p_Wc2, (const float*)p_bc2, (float*)p_ac2);
    gather2_kernel<<<NP*32/256, 256>>>();

    colmax_kernel<<<NBATCH*32, 256>>>();
    batchvec_kernel<<<NBATCH, 256>>>(glob_w, glob_b, h1_w, h1_b);

    gemm_kernel<256, 256, 1, 1><<<dim3(NP/128, 256/64), 256>>>(
        (const float*)p_f2, h1_w, (const float*)p_tvec, (float*)p_h);

    final_kernel<<<NP*32/256, 256>>>(x, h2_w, h2_b, thresh, sharp, scale, out);
    (void)in_sizes; (void)n_in; (void)out_size;
}

// round 10
// speedup vs baseline: 1.4075x; 1.0159x over previous
#include <cuda_runtime.h>
#include <math.h>

#define NBATCH 4
#define NPTS   8192
#define NP     32768   // NBATCH*NPTS
#define KNN    16

#define KT      128            // knn threads per block
#define KCHUNK  2048           // candidates per smem tile
#define NCHUNK  (NPTS/KCHUNK)  // 4
#define KBLK    128            // block size for phase-A minima (64 minima total)
#define RP      12             // ring slots per stream per chunk
#define NSTREAM 4
#define RING    (RP*NSTREAM)   // 48
#define KNN_SMEM (KCHUNK*16 + RING*KT*4 + RING*KT*4)   // 32KB + 24KB + 24KB

// ---------------- scratch (static device globals; no allocs allowed) ----------------
__device__ float4 g_coords4[NP];    // {x, y, z, |p|^2}
__device__ float g_act1[NP*80];     // [f0(64) | coords(3) | zeros(13)]
__device__ int   g_idx[NP*KNN];     // global neighbor indices
__device__ float g_Wc1[80*256];     // combined stage-1 weights [k][n], n<128 -> a, n>=128 -> c
__device__ float g_bc1[256];
__device__ float g_Wc2[144*512];
__device__ float g_bc2[512];
__device__ float g_ac1[NP*256];     // [a1(128) | c1(128)]
__device__ float g_act2[NP*144];    // [f1(128) | coords(3) | zeros(13)]
__device__ float g_ac2[NP*512];     // [a2(256) | c2(256)]
__device__ float g_f2[NP*256];
__device__ float g_h[NP*256];
__device__ int   g_gmax[NBATCH*256];
__device__ float g_tvec[NBATCH*256];

// ---------------- build combined weights ----------------
__global__ void build_weights(const float* __restrict__ b1w, const float* __restrict__ b1b,
                              const float* __restrict__ b2w, const float* __restrict__ b2b) {
    int t = threadIdx.x;
    for (int i = t; i < 80*256; i += 256) {
        int k = i >> 8, n = i & 255;
        int nc = n & 127; bool isC = n >= 128;
        float v = 0.f;
        if (k < 64) {
            float wa = b1w[k*128 + nc];
            float wb = b1w[(64+k)*128 + nc];
            v = isC ? wb : (wa - wb);
        } else if (k < 67) {
            float wp = b1w[(128 + (k-64))*128 + nc];
            v = isC ? wp : -wp;
        }
        g_Wc1[i] = v;
    }
    for (int n = t; n < 256; n += 256) g_bc1[n] = (n < 128) ? b1b[n] : 0.f;
    for (int i = t; i < 144*512; i += 256) {
        int k = i >> 9, n = i & 511;
        int nc = n & 255; bool isC = n >= 256;
        float v = 0.f;
        if (k < 128) {
            float wa = b2w[k*256 + nc];
            float wb = b2w[(128+k)*256 + nc];
            v = isC ? wb : (wa - wb);
        } else if (k < 131) {
            float wp = b2w[(256 + (k-128))*256 + nc];
            v = isC ? wp : -wp;
        }
        g_Wc2[i] = v;
    }
    for (int n = t; n < 512; n += 256) g_bc2[n] = (n < 256) ? b2b[n] : 0.f;
}

// ---------------- prep: coords + stem ----------------
__global__ void prep_kernel(const float* __restrict__ x,
                            const float* __restrict__ pa, const float* __restrict__ pb,
                            const float* __restrict__ pc,
                            const float* __restrict__ sw, const float* __restrict__ sb) {
    __shared__ float w[256];
    __shared__ float bsh[64];
    if (threadIdx.x < 256) w[threadIdx.x] = sw[threadIdx.x];
    if (threadIdx.x < 64)  bsh[threadIdx.x] = sb[threadIdx.x];
    __syncthreads();
    int i = blockIdx.x * blockDim.x + threadIdx.x;
    if (i >= NP) return;
    float4 xv = ((const float4*)x)[i];
    float z = (*pa) * xv.z + (*pb) * xv.w + (*pc);
    float nsq = fmaf(xv.x, xv.x, fmaf(xv.y, xv.y, z*z));
    g_coords4[i] = make_float4(xv.x, xv.y, z, nsq);
    float* a = &g_act1[i*80];
    #pragma unroll 8
    for (int o = 0; o < 64; o++) {
        float s = bsh[o];
        s = fmaf(xv.x, w[o],      s);
        s = fmaf(xv.y, w[64+o],   s);
        s = fmaf(xv.z, w[128+o],  s);
        s = fmaf(xv.w, w[192+o],  s);
        a[o] = fmaxf(s, 0.f);
    }
    a[64] = xv.x; a[65] = xv.y; a[66] = z;
    #pragma unroll
    for (int o = 67; o < 80; o++) a[o] = 0.f;
}

// ---------------- KNN: two-phase threshold + 4-stream ring collection ----------------
// Surrogate d' = |p|^2 - 2 q.p (monotone per query in true distance).
// Phase A: 64 block-minima -> tau = 16th smallest block-min (upper bound on true 16th).
// Phase B: four independent streams per thread (chunk quarters) for ILP; predicated
// smem ring push; drain per chunk into top-16 regs; threshold tightens per chunk.
__global__ __launch_bounds__(KT) void knn_kernel() {
    extern __shared__ char sm[];
    float4* tile   = (float4*)sm;                              // KCHUNK float4
    float*  ring_d = (float*)(sm + KCHUNK*16);                 // [RING][KT]
    int*    ring_i = (int*)  (sm + KCHUNK*16 + RING*KT*4);     // [RING][KT]

    int b    = blockIdx.x >> 6;                 // 64 query-blocks per batch
    int n    = (blockIdx.x & 63)*KT + threadIdx.x;
    int base = b*NPTS;
    float4 q = g_coords4[base + n];
    float nqx = -2.f*q.x, nqy = -2.f*q.y, nqz = -2.f*q.z;

    // ---- Phase A: threshold ----
    float s[KNN];
    #pragma unroll
    for (int t = 0; t < KNN; t++) s[t] = 3.4e38f;

    for (int c = 0; c < NCHUNK; c++) {
        __syncthreads();
        for (int i = threadIdx.x; i < KCHUNK; i += KT)
            tile[i] = g_coords4[base + c*KCHUNK + i];
        __syncthreads();
        for (int blk = 0; blk < KCHUNK/KBLK; blk++) {
            const float4* tb = &tile[blk*KBLK];
            float m0 = 3.4e38f, m1 = 3.4e38f, m2 = 3.4e38f, m3 = 3.4e38f;
            #pragma unroll 4
            for (int j = 0; j < KBLK; j += 4) {
                float4 p0 = tb[j+0], p1 = tb[j+1], p2 = tb[j+2], p3 = tb[j+3];
                m0 = fminf(m0, fmaf(p0.z, nqz, fmaf(p0.y, nqy, fmaf(p0.x, nqx, p0.w))));
                m1 = fminf(m1, fmaf(p1.z, nqz, fmaf(p1.y, nqy, fmaf(p1.x, nqx, p1.w))));
                m2 = fminf(m2, fmaf(p2.z, nqz, fmaf(p2.y, nqy, fmaf(p2.x, nqx, p2.w))));
                m3 = fminf(m3, fmaf(p3.z, nqz, fmaf(p3.y, nqy, fmaf(p3.x, nqx, p3.w))));
            }
            float m = fminf(fminf(m0, m1), fminf(m2, m3));
            // branchless insert into 16 smallest (s ascending)
            #pragma unroll
            for (int t = 0; t < KNN; t++) {
                float lo = fminf(s[t], m);
                m = fmaxf(s[t], m);
                s[t] = lo;
            }
        }
    }
    float tau = s[KNN-1];
    int tb_ = __float_as_int(tau);
    tb_ += (tau >= 0.f) ? 1 : -1;          // nextafter(tau, +inf): accept d <= tau via d < worst
    float worst = __int_as_float(tb_);

    // ---- Phase B: 4-stream collect + drain ----
    float bd[KNN]; int bi[KNN];
    #pragma unroll
    for (int t = 0; t < KNN; t++) { bd[t] = worst; bi[t] = 0; }

    for (int c = 0; c < NCHUNK; c++) {
        __syncthreads();
        for (int i = threadIdx.x; i < KCHUNK; i += KT)
            tile[i] = g_coords4[base + c*KCHUNK + i];
        __syncthreads();
        int cnt0 = 0, cnt1 = 0, cnt2 = 0, cnt3 = 0;
        int jbase = c*KCHUNK;
        const int Q = KCHUNK/4;   // 512
        #pragma unroll 2
        for (int j = 0; j < Q; j++) {
            float4 p0 = tile[j];
            float4 p1 = tile[j + Q];
            float4 p2 = tile[j + 2*Q];
            float4 p3 = tile[j + 3*Q];
            float d0 = fmaf(p0.z, nqz, fmaf(p0.y, nqy, fmaf(p0.x, nqx, p0.w)));
            float d1 = fmaf(p1.z, nqz, fmaf(p1.y, nqy, fmaf(p1.x, nqx, p1.w)));
            float d2 = fmaf(p2.z, nqz, fmaf(p2.y, nqy, fmaf(p2.x, nqx, p2.w)));
            float d3 = fmaf(p3.z, nqz, fmaf(p3.y, nqy, fmaf(p3.x, nqx, p3.w)));
            if (d0 < worst && cnt0 < RP) {
                ring_d[(0*RP + cnt0)*KT + threadIdx.x] = d0;
                ring_i[(0*RP + cnt0)*KT + threadIdx.x] = jbase + j;
                cnt0++;
            }
            if (d1 < worst && cnt1 < RP) {
                ring_d[(1*RP + cnt1)*KT + threadIdx.x] = d1;
                ring_i[(1*RP + cnt1)*KT + threadIdx.x] = jbase + j + Q;
                cnt1++;
            }
            if (d2 < worst && cnt2 < RP) {
                ring_d[(2*RP + cnt2)*KT + threadIdx.x] = d2;
                ring_i[(2*RP + cnt2)*KT + threadIdx.x] = jbase + j + 2*Q;
                cnt2++;
            }
            if (d3 < worst && cnt3 < RP) {
                ring_d[(3*RP + cnt3)*KT + threadIdx.x] = d3;
                ring_i[(3*RP + cnt3)*KT + threadIdx.x] = jbase + j + 3*Q;
                cnt3++;
            }
        }
        // drain rings into top-16 registers (rare, small)
        int cnts[NSTREAM] = {cnt0, cnt1, cnt2, cnt3};
        #pragma unroll
        for (int st = 0; st < NSTREAM; st++) {
            for (int k = 0; k < cnts[st]; k++) {
                float d = ring_d[(st*RP + k)*KT + threadIdx.x];
                int  ji = ring_i[(st*RP + k)*KT + threadIdx.x];
                float w = bd[0]; int ws = 0;
                #pragma unroll
                for (int t = 1; t < KNN; t++) if (bd[t] > w) { w = bd[t]; ws = t; }
                if (d < w) { bd[ws] = d; bi[ws] = ji; }
            }
        }
        // tighten threshold
        float w = bd[0];
        #pragma unroll
        for (int t = 1; t < KNN; t++) w = fmaxf(w, bd[t]);
        worst = w;
    }

    int qg = base + n;
    #pragma unroll
    for (int t = 0; t < KNN; t++) g_idx[qg*KNN + t] = base + bi[t];
}

// ---------------- fp32 GEMM: C[M,NT] = act(A[M,KP]@W[KP,NT] + bias) ----------------
// BM=128, BN=128, BK=16, 256 threads, 8x8 per thread. As stored k-major for LDS.128.
// BIASMODE 0: bias[n]; 1: bias[(row>>13)*256 + n] (per-batch vector, NT must be 256)
template<int KP, int NT, int BIASMODE, int RELU>
__global__ __launch_bounds__(256) void gemm_kernel(const float* __restrict__ A,
                                                   const float* __restrict__ W,
                                                   const float* __restrict__ bias,
                                                   float* __restrict__ C) {
    __shared__ float As[16][132];   // k-major; 132*4=528B rows (16B aligned)
    __shared__ float Bs[16][128];
    int tid = threadIdx.x;
    int row0 = blockIdx.x * 128;
    int col0 = blockIdx.y * 128;
    int m0 = (tid >> 4) * 8;
    int n0 = (tid & 15) * 8;
    float acc[8][8];
    #pragma unroll
    for (int i = 0; i < 8; i++)
        #pragma unroll
        for (int j = 0; j < 8; j++) acc[i][j] = 0.f;

    for (int k0 = 0; k0 < KP; k0 += 16) {
        // load A tile 128x16 (512 float4 across 256 threads, transposed into As)
        #pragma unroll
        for (int i = 0; i < 2; i++) {
            int lin = tid + i*256;
            int r = lin >> 2, kc = (lin & 3) * 4;
            float4 av = *(const float4*)&A[(row0 + r)*KP + k0 + kc];
            As[kc+0][r] = av.x; As[kc+1][r] = av.y;
            As[kc+2][r] = av.z; As[kc+3][r] = av.w;
        }
        // load W tile 16x128 (512 float4)
        #pragma unroll
        for (int i = 0; i < 2; i++) {
            int lin = tid + i*256;
            int kk = lin >> 5, cc = (lin & 31) * 4;
            *(float4*)&Bs[kk][cc] = *(const float4*)&W[(k0 + kk)*NT + col0 + cc];
        }
        __syncthreads();
        #pragma unroll
        for (int kk = 0; kk < 16; kk++) {
            float4 a0 = *(float4*)&As[kk][m0];
            float4 a1 = *(float4*)&As[kk][m0+4];
            float4 b0 = *(float4*)&Bs[kk][n0];
            float4 b1 = *(float4*)&Bs[kk][n0+4];
            float ar[8] = {a0.x, a0.y, a0.z, a0.w, a1.x, a1.y, a1.z, a1.w};
            float br[8] = {b0.x, b0.y, b0.z, b0.w, b1.x, b1.y, b1.z, b1.w};
            #pragma unroll
            for (int i = 0; i < 8; i++) {
                #pragma unroll
                for (int j = 0; j < 8; j++)
                    acc[i][j] = fmaf(ar[i], br[j], acc[i][j]);
            }
        }
        __syncthreads();
    }
    #pragma unroll
    for (int i = 0; i < 8; i++) {
        int row = row0 + m0 + i;
        #pragma unroll
        for (int jj = 0; jj < 2; jj++) {
            float4 r;
            float bx[4];
            #pragma unroll
            for (int j = 0; j < 4; j++) {
                int col = col0 + n0 + jj*4 + j;
                bx[j] = (BIASMODE == 0) ? bias[col] : bias[(row >> 13)*256 + col];
            }
            r.x = acc[i][jj*4+0] + bx[0]; r.y = acc[i][jj*4+1] + bx[1];
            r.z = acc[i][jj*4+2] + bx[2]; r.w = acc[i][jj*4+3] + bx[3];
            if (RELU) {
                r.x = fmaxf(r.x, 0.f); r.y = fmaxf(r.y, 0.f);
                r.z = fmaxf(r.z, 0.f); r.w = fmaxf(r.w, 0.f);
            }
            *(float4*)&C[row*NT + col0 + n0 + jj*4] = r;
        }
    }
}

// ---------------- gather-max stage 1 ----------------
__global__ void gather1_kernel() {
    int wid  = (blockIdx.x * blockDim.x + threadIdx.x) >> 5;
    int lane = threadIdx.x & 31;
    if (wid >= NP) return;
    const int* idx = &g_idx[wid*KNN];
    float4 mv = make_float4(-3.4e38f, -3.4e38f, -3.4e38f, -3.4e38f);
    #pragma unroll
    for (int t = 0; t < KNN; t++) {
        int j = idx[t];
        float4 v = *(const float4*)&g_ac1[j*256 + 128 + lane*4];
        mv.x = fmaxf(mv.x, v.x); mv.y = fmaxf(mv.y, v.y);
        mv.z = fmaxf(mv.z, v.z); mv.w = fmaxf(mv.w, v.w);
    }
    float4 a = *(const float4*)&g_ac1[wid*256 + lane*4];
    float4 o;
    o.x = fmaxf(a.x + mv.x, 0.f); o.y = fmaxf(a.y + mv.y, 0.f);
    o.z = fmaxf(a.z + mv.z, 0.f); o.w = fmaxf(a.w + mv.w, 0.f);
    *(float4*)&g_act2[wid*144 + lane*4] = o;
    if (lane < 16) {
        float v = (lane < 3) ? ((const float*)g_coords4)[wid*4 + lane] : 0.f;
        g_act2[wid*144 + 128 + lane] = v;
    }
}

// ---------------- gather-max stage 2 ----------------
__global__ void gather2_kernel() {
    int wid  = (blockIdx.x * blockDim.x + threadIdx.x) >> 5;
    int lane = threadIdx.x & 31;
    if (wid >= NP) return;
    const int* idx = &g_idx[wid*KNN];
    float4 m0 = make_float4(-3.4e38f, -3.4e38f, -3.4e38f, -3.4e38f);
    float4 m1 = m0;
    #pragma unroll
    for (int t = 0; t < KNN; t++) {
        int j = idx[t];
        float4 v0 = *(const float4*)&g_ac2[j*512 + 256 + lane*4];
        float4 v1 = *(const float4*)&g_ac2[j*512 + 384 + lane*4];
        m0.x = fmaxf(m0.x, v0.x); m0.y = fmaxf(m0.y, v0.y);
        m0.z = fmaxf(m0.z, v0.z); m0.w = fmaxf(m0.w, v0.w);
        m1.x = fmaxf(m1.x, v1.x); m1.y = fmaxf(m1.y, v1.y);
        m1.z = fmaxf(m1.z, v1.z); m1.w = fmaxf(m1.w, v1.w);
    }
    float4 a0 = *(const float4*)&g_ac2[wid*512 + lane*4];
    float4 a1 = *(const float4*)&g_ac2[wid*512 + 128 + lane*4];
    float4 o0, o1;
    o0.x = fmaxf(a0.x + m0.x, 0.f); o0.y = fmaxf(a0.y + m0.y, 0.f);
    o0.z = fmaxf(a0.z + m0.z, 0.f); o0.w = fmaxf(a0.w + m0.w, 0.f);
    o1.x = fmaxf(a1.x + m1.x, 0.f); o1.y = fmaxf(a1.y + m1.y, 0.f);
    o1.z = fmaxf(a1.z + m1.z, 0.f); o1.w = fmaxf(a1.w + m1.w, 0.f);
    *(float4*)&g_f2[wid*256 + lane*4]       = o0;
    *(float4*)&g_f2[wid*256 + 128 + lane*4] = o1;
}

// ---------------- global max pooling ----------------
__global__ void zero_gmax_kernel() {
    int i = threadIdx.x;
    if (i < NBATCH*256) g_gmax[i] = 0;   // 0.0f bits; all f2 >= 0
}

__global__ void colmax_kernel() {
    int b = blockIdx.x >> 5;
    int chunk = blockIdx.x & 31;
    int c = threadIdx.x;
    int base = b*NPTS + chunk*256;
    float m = 0.f;
    #pragma unroll 4
    for (int p = 0; p < 256; p++) m = fmaxf(m, g_f2[(base + p)*256 + c]);
    atomicMax(&g_gmax[b*256 + c], __float_as_int(m));
}

// ---------------- per-batch vectors ----------------
__global__ void batchvec_kernel(const float* __restrict__ globw, const float* __restrict__ globb,
                                const float* __restrict__ h1w, const float* __restrict__ h1b) {
    int b = blockIdx.x, n = threadIdx.x;
    __shared__ float gm[256], gg[256];
    gm[n] = __int_as_float(g_gmax[b*256 + n]);
    __syncthreads();
    float s = globb[n];
    #pragma unroll 8
    for (int k = 0; k < 256; k++) s = fmaf(gm[k], globw[k*256 + n], s);
    gg[n] = fmaxf(s, 0.f);
    __syncthreads();
    float t = h1b[n];
    #pragma unroll 8
    for (int k = 0; k < 256; k++) t = fmaf(gg[k], h1w[(256 + k)*256 + n], t);
    g_tvec[b*256 + n] = t;
}

// ---------------- final head ----------------
__global__ void final_kernel(const float* __restrict__ x,
                             const float* __restrict__ h2w, const float* __restrict__ h2b,
                             const float* __restrict__ pthresh, const float* __restrict__ psharp,
                             const float* __restrict__ pscale, float* __restrict__ out) {
    int wid  = (blockIdx.x * blockDim.x + threadIdx.x) >> 5;
    int lane = threadIdx.x & 31;
    if (wid >= NP) return;
    const float* h = &g_h[wid*256];
    float s0 = 0.f, s1 = 0.f, s2 = 0.f;
    #pragma unroll
    for (int m = 0; m < 8; m++) {
        int k = lane + 32*m;
        float hv = h[k];
        s0 = fmaf(hv, h2w[k*3+0], s0);
        s1 = fmaf(hv, h2w[k*3+1], s1);
        s2 = fmaf(hv, h2w[k*3+2], s2);
    }
    #pragma unroll
    for (int o = 16; o; o >>= 1) {
        s0 += __shfl_down_sync(0xFFFFFFFFu, s0, o);
        s1 += __shfl_down_sync(0xFFFFFFFFu, s1, o);
        s2 += __shfl_down_sync(0xFFFFFFFFu, s2, o);
    }
    if (lane == 0) {
        float hag = x[wid*4 + 3];
        float t = (*psharp) * ((*pthresh) - hag);
        float bias = (*pscale) / (1.f + expf(-t));
        out[wid*3+0] = s0 + h2b[0] + bias;
        out[wid*3+1] = s1 + h2b[1];
        out[wid*3+2] = s2 + h2b[2];
    }
}

// ---------------- launch ----------------
extern "C" void kernel_launch(void* const* d_in, const int* in_sizes, int n_in,
                              void* d_out, int out_size) {
    const float* x      = (const float*)d_in[0];
    const float* hmix_a = (const float*)d_in[1];
    const float* hmix_b = (const float*)d_in[2];
    const float* hmix_c = (const float*)d_in[3];
    const float* stem_w = (const float*)d_in[4];
    const float* stem_b = (const float*)d_in[5];
    const float* b1_w   = (const float*)d_in[6];
    const float* b1_b   = (const float*)d_in[7];
    const float* b2_w   = (const float*)d_in[8];
    const float* b2_b   = (const float*)d_in[9];
    const float* glob_w = (const float*)d_in[10];
    const float* glob_b = (const float*)d_in[11];
    const float* h1_w   = (const float*)d_in[12];
    const float* h1_b   = (const float*)d_in[13];
    const float* h2_w   = (const float*)d_in[14];
    const float* h2_b   = (const float*)d_in[15];
    const float* thresh = (const float*)d_in[16];
    const float* sharp  = (const float*)d_in[17];
    const float* scale  = (const float*)d_in[18];
    float* out = (float*)d_out;

    void *p_act1, *p_Wc1, *p_bc1, *p_ac1, *p_act2, *p_Wc2, *p_bc2, *p_ac2, *p_f2, *p_tvec, *p_h;
    cudaGetSymbolAddress(&p_act1, g_act1);
    cudaGetSymbolAddress(&p_Wc1,  g_Wc1);
    cudaGetSymbolAddress(&p_bc1,  g_bc1);
    cudaGetSymbolAddress(&p_ac1,  g_ac1);
    cudaGetSymbolAddress(&p_act2, g_act2);
    cudaGetSymbolAddress(&p_Wc2,  g_Wc2);
    cudaGetSymbolAddress(&p_bc2,  g_bc2);
    cudaGetSymbolAddress(&p_ac2,  g_ac2);
    cudaGetSymbolAddress(&p_f2,   g_f2);
    cudaGetSymbolAddress(&p_tvec, g_tvec);
    cudaGetSymbolAddress(&p_h,    g_h);

    cudaFuncSetAttribute(knn_kernel, cudaFuncAttributeMaxDynamicSharedMemorySize, KNN_SMEM);

    build_weights<<<1, 256>>>(b1_w, b1_b, b2_w, b2_b);
    prep_kernel<<<NP/256, 256>>>(x, hmix_a, hmix_b, hmix_c, stem_w, stem_b);
    zero_gmax_kernel<<<1, 1024>>>();
    knn_kernel<<<NBATCH*64, KT, KNN_SMEM>>>();

    gemm_kernel<80, 256, 0, 0><<<dim3(NP/128, 256/128), 256>>>(
        (const float*)p_act1, (const float*)p_Wc1, (const float*)p_bc1, (float*)p_ac1);
    gather1_kernel<<<NP*32/256, 256>>>();

    gemm_kernel<144, 512, 0, 0><<<dim3(NP/128, 512/128), 256>>>(
        (const float*)p_act2, (const float*)p_Wc2, (const float*)p_bc2, (float*)p_ac2);
    gather2_kernel<<<NP*32/256, 256>>>();

    colmax_kernel<<<NBATCH*32, 256>>>();
    batchvec_kernel<<<NBATCH, 256>>>(glob_w, glob_b, h1_w, h1_b);

    gemm_kernel<256, 256, 1, 1><<<dim3(NP/128, 256/128), 256>>>(
        (const float*)p_f2, h1_w, (const float*)p_tvec, (float*)p_h);

    final_kernel<<<NP*32/256, 256>>>(x, h2_w, h2_b, thresh, sharp, scale, out);
    (void)in_sizes; (void)n_in; (void)out_size;
}